// round 13
// baseline (speedup 1.0000x reference)
#include <cuda_runtime.h>
#include <cuda_fp16.h>
#include <math.h>

// Problem constants (match reference)
#define Wd 96
#define Hd 96
#define Dd 64
#define Ad 90
#define Ud 96
#define Vd 64
#define NSTEPS 194          // H + W + 2
#define NRAYS  (Ad * Ud)    // 8640
#define RPB    4            // rays per block in accumulate kernel
#define NVOX   (Wd * Hd * Dd)

// Static device scratch (no allocations allowed).
// Packed trace: .x = voxel base offset (i*H*D + j*D), .y = weight bits.
__device__ int2    g_trace[NRAYS * NSTEPS];
__device__ int     g_cnt[NRAYS];
__device__ __half2 g_volh[NVOX / 2];     // fp16 copy of the volume

__device__ __forceinline__ void t_for(float p0, float dp, float pmin, float pmax,
                                      float& lo, float& hi) {
    const float EPS = 1e-12f;
    bool par = fabsf(dp) < EPS;
    float safe = par ? 1.0f : dp;
    float t0 = (pmin - p0) / safe;
    float t1 = (pmax - p0) / safe;
    lo = fminf(t0, t1);
    hi = fmaxf(t0, t1);
    bool inside = (p0 >= pmin) && (p0 <= pmax);
    if (par) {
        lo = inside ? -INFINITY : INFINITY;
        hi = inside ?  INFINITY : -INFINITY;
    }
}

// Convert the f32 volume to fp16 (element order preserved).
__global__ __launch_bounds__(256) void vol_to_half_kernel(const float* __restrict__ vol) {
    int idx = blockIdx.x * blockDim.x + threadIdx.x;
    int n2  = NVOX / 2;
    for (int k = idx; k < n2; k += gridDim.x * blockDim.x) {
        float2 f = ((const float2*)vol)[k];
        g_volh[k] = __floats2half2_rn(f.x, f.y);
    }
}

// One thread per ray — R2-exact version (measured 13.6us, rel_err 9.9e-5).
__global__ __launch_bounds__(64) void siddon_trace_kernel() {
    int r = blockIdx.x * blockDim.x + threadIdx.x;
    if (r >= NRAYS) return;

    const float EPS  = 1e-12f;
    const float DIAG = 1.41421356237309515f;  // f32(sqrt(2))

    int a  = r / Ud;
    int ui = r % Ud;

    const float ang_step = 3.14159274101257324f / 90.0f;
    float ang = (float)a * ang_step;
    float ct = (float)cos((double)ang);
    float st = (float)sin((double)ang);

    float u  = (float)ui - 47.5f;
    float dx = ct, dy = st;
    float x0 = -u * st;
    float y0 =  u * ct;

    const float pmin = -47.5f, pmax = 47.5f;

    float tx0, tx1, ty0, ty1;
    t_for(x0, dx, pmin, pmax, tx0, tx1);
    t_for(y0, dy, pmin, pmax, ty0, ty1);

    float t_entry = fmaxf(tx0, ty0);
    float t_exit  = fminf(tx1, ty1);
    bool  alive   = t_entry < t_exit;
    float te  = alive ? t_entry : 0.0f;
    float tex = alive ? t_exit  : 0.0f;

    float xe = x0 + te * dx;
    float ye = y0 + te * dy;

    int i = (int)fminf(fmaxf(rintf(xe + 47.5f), 0.0f), (float)(Wd - 1));
    int j = (int)fminf(fmaxf(rintf(ye + 47.5f), 0.0f), (float)(Hd - 1));

    float x = xe, y = ye, t = te;
    float wscale = DIAG / fmaxf(fabsf(dx) + fabsf(dy), EPS);

    bool okx = fabsf(dx) > EPS;
    bool oky = fabsf(dy) > EPS;
    float inv_dx = okx ? (1.0f / dx) : 0.0f;
    float inv_dy = oky ? (1.0f / dy) : 0.0f;

    float xoff = (dx > 0.0f) ? (0.5f - 47.5f) : (-0.5f - 47.5f);
    float yoff = (dy > 0.0f) ? (0.5f - 47.5f) : (-0.5f - 47.5f);
    int   istep = (dx > 0.0f) ? 1 : -1;
    int   jstep = (dy > 0.0f) ? 1 : -1;

    int cnt  = 0;
    int base = r * NSTEPS;

    for (int s = 0; s < NSTEPS; s++) {
        if (!alive) break;
        bool valid = (t < tex - EPS);

        float tx = okx ? (((float)i + xoff) - x) * inv_dx : INFINITY;
        float ty = oky ? (((float)j + yoff) - y) * inv_dy : INFINITY;

        float dt = fminf(fminf(tx, ty), tex - t);
        float w  = fmaxf(0.0f, dt * wscale);

        if (valid && w > 0.0f) {
            int2 e;
            e.x = i * (Hd * Dd) + j * Dd;
            e.y = __float_as_int(w);
            g_trace[base + cnt] = e;
            cnt++;
        }

        int i_n = i + ((tx <= ty) ? istep : 0);
        int j_n = j + ((ty <= tx) ? jstep : 0);
        bool inb = (i_n >= 0) && (i_n < Wd) && (j_n >= 0) && (j_n < Hd);

        if (valid) {
            i = i_n; j = j_n;
            x += dx * dt;
            y += dy * dt;
            t += dt;
        }
        alive = valid && inb;
    }
    g_cnt[r] = cnt;
}

// R2-exact accum structure; only change: volume loads are half2 (128B per
// warp per step = 1 L1 wavefront instead of 2). Accumulation stays f32.
__global__ __launch_bounds__(32 * RPB) void siddon_accum_kernel(
        float* __restrict__ out) {
    __shared__ int2 s_t[RPB][NSTEPS];

    int yy  = threadIdx.y;       // ray within block (== warp id)
    int x   = threadIdx.x;       // lane: covers v = 2x, 2x+1
    int ray = blockIdx.x * RPB + yy;

    int cnt  = g_cnt[ray];       // uniform per warp -> broadcast load
    int base = ray * NSTEPS;

    for (int n = x; n < cnt; n += 32)
        s_t[yy][n] = g_trace[base + n];
    __syncwarp();

    float a0x = 0.0f, a0y = 0.0f, a1x = 0.0f, a1y = 0.0f;

    int n = 0;
    for (; n + 1 < cnt; n += 2) {
        int2 e0 = s_t[yy][n + 0];
        int2 e1 = s_t[yy][n + 1];
        float2 v0 = __half22float2(g_volh[(e0.x >> 1) + x]);
        float2 v1 = __half22float2(g_volh[(e1.x >> 1) + x]);
        float  w0 = __int_as_float(e0.y);
        float  w1 = __int_as_float(e1.y);
        a0x += v0.x * w0;  a0y += v0.y * w0;
        a1x += v1.x * w1;  a1y += v1.y * w1;
    }
    if (n < cnt) {
        int2 e = s_t[yy][n];
        float2 v = __half22float2(g_volh[(e.x >> 1) + x]);
        float  w = __int_as_float(e.y);
        a0x += v.x * w;  a0y += v.y * w;
    }

    int a  = ray / Ud;
    int ui = ray % Ud;
    float2 res;
    res.x = a0x + a1x;
    res.y = a0y + a1y;
    // output layout (B,C,U,A,V): float2 index = (u*A + a)*32 + lane
    ((float2*)out)[(ui * Ad + a) * 32 + x] = res;
}

extern "C" void kernel_launch(void* const* d_in, const int* in_sizes, int n_in,
                              void* d_out, int out_size) {
    const float* vol = (const float*)d_in[0];
    float* out = (float*)d_out;

    vol_to_half_kernel<<<148, 256>>>(vol);
    siddon_trace_kernel<<<(NRAYS + 63) / 64, 64>>>();

    dim3 blk(32, RPB);                 // 128 threads
    dim3 grd(NRAYS / RPB);             // 2160 blocks
    siddon_accum_kernel<<<grd, blk>>>(out);
}

// round 15
// speedup vs baseline: 1.0786x; 1.0786x over previous
#include <cuda_runtime.h>
#include <cuda_fp16.h>
#include <math.h>

// Problem constants (match reference)
#define Wd 96
#define Hd 96
#define Dd 64
#define Ad 90
#define Ud 96
#define Vd 64
#define NSTEPS 194          // H + W + 2  (x8B = 1552B rows, 16B-aligned)
#define NRAYS  (Ad * Ud)    // 8640
#define RPB    4            // rays per block in accumulate kernel
#define NVOX   (Wd * Hd * Dd)
#define TRACE_BLOCKS ((NRAYS + 63) / 64)   // 135
#define CONV_BLOCKS  1024

// Static device scratch (no allocations allowed).
// Packed trace: .x = voxel base offset (i*H*D + j*D), .y = weight bits.
__device__ int2    g_trace[NRAYS * NSTEPS];
__device__ int     g_cnt[NRAYS];
__device__ __half2 g_volh[NVOX / 2];     // fp16 copy of the volume

__device__ __forceinline__ void t_for(float p0, float dp, float pmin, float pmax,
                                      float& lo, float& hi) {
    const float EPS = 1e-12f;
    bool par = fabsf(dp) < EPS;
    float safe = par ? 1.0f : dp;
    float t0 = (pmin - p0) / safe;
    float t1 = (pmax - p0) / safe;
    lo = fminf(t0, t1);
    hi = fmaxf(t0, t1);
    bool inside = (p0 >= pmin) && (p0 <= pmax);
    if (par) {
        lo = inside ? -INFINITY : INFINITY;
        hi = inside ?  INFINITY : -INFINITY;
    }
}

// Heterogeneous launch: blocks [0, TRACE_BLOCKS) run the R2-exact serial
// Siddon trace (1 thread/ray); the remaining blocks convert the volume to
// fp16 in parallel (hidden under the latency-bound trace).
__global__ __launch_bounds__(64) void siddon_trace_conv_kernel(
        const float* __restrict__ vol) {
    if (blockIdx.x >= TRACE_BLOCKS) {
        // ---- conversion blocks ----
        int idx = (blockIdx.x - TRACE_BLOCKS) * 64 + threadIdx.x;
        int n2  = NVOX / 2;
        for (int k = idx; k < n2; k += CONV_BLOCKS * 64) {
            float2 f = ((const float2*)vol)[k];
            g_volh[k] = __floats2half2_rn(f.x, f.y);
        }
        return;
    }

    // ---- trace blocks (R2-exact) ----
    int r = blockIdx.x * 64 + threadIdx.x;
    if (r >= NRAYS) return;

    const float EPS  = 1e-12f;
    const float DIAG = 1.41421356237309515f;  // f32(sqrt(2))

    int a  = r / Ud;
    int ui = r % Ud;

    const float ang_step = 3.14159274101257324f / 90.0f;
    float ang = (float)a * ang_step;
    float ct = (float)cos((double)ang);
    float st = (float)sin((double)ang);

    float u  = (float)ui - 47.5f;
    float dx = ct, dy = st;
    float x0 = -u * st;
    float y0 =  u * ct;

    const float pmin = -47.5f, pmax = 47.5f;

    float tx0, tx1, ty0, ty1;
    t_for(x0, dx, pmin, pmax, tx0, tx1);
    t_for(y0, dy, pmin, pmax, ty0, ty1);

    float t_entry = fmaxf(tx0, ty0);
    float t_exit  = fminf(tx1, ty1);
    bool  alive   = t_entry < t_exit;
    float te  = alive ? t_entry : 0.0f;
    float tex = alive ? t_exit  : 0.0f;

    float xe = x0 + te * dx;
    float ye = y0 + te * dy;

    int i = (int)fminf(fmaxf(rintf(xe + 47.5f), 0.0f), (float)(Wd - 1));
    int j = (int)fminf(fmaxf(rintf(ye + 47.5f), 0.0f), (float)(Hd - 1));

    float x = xe, y = ye, t = te;
    float wscale = DIAG / fmaxf(fabsf(dx) + fabsf(dy), EPS);

    bool okx = fabsf(dx) > EPS;
    bool oky = fabsf(dy) > EPS;
    float inv_dx = okx ? (1.0f / dx) : 0.0f;
    float inv_dy = oky ? (1.0f / dy) : 0.0f;

    float xoff = (dx > 0.0f) ? (0.5f - 47.5f) : (-0.5f - 47.5f);
    float yoff = (dy > 0.0f) ? (0.5f - 47.5f) : (-0.5f - 47.5f);
    int   istep = (dx > 0.0f) ? 1 : -1;
    int   jstep = (dy > 0.0f) ? 1 : -1;

    int cnt  = 0;
    int base = r * NSTEPS;

    for (int s = 0; s < NSTEPS; s++) {
        if (!alive) break;
        bool valid = (t < tex - EPS);

        float tx = okx ? (((float)i + xoff) - x) * inv_dx : INFINITY;
        float ty = oky ? (((float)j + yoff) - y) * inv_dy : INFINITY;

        float dt = fminf(fminf(tx, ty), tex - t);
        float w  = fmaxf(0.0f, dt * wscale);

        if (valid && w > 0.0f) {
            int2 e;
            e.x = i * (Hd * Dd) + j * Dd;
            e.y = __float_as_int(w);
            g_trace[base + cnt] = e;
            cnt++;
        }

        int i_n = i + ((tx <= ty) ? istep : 0);
        int j_n = j + ((ty <= tx) ? jstep : 0);
        bool inb = (i_n >= 0) && (i_n < Wd) && (j_n >= 0) && (j_n < Hd);

        if (valid) {
            i = i_n; j = j_n;
            x += dx * dt;
            y += dy * dt;
            t += dt;
        }
        alive = valid && inb;
    }
    g_cnt[r] = cnt;
}

// Accum: one warp per ray, half2 volume loads (1 L1 wavefront per step),
// trace entries read pairwise via LDS.128. f32 accumulation.
__global__ __launch_bounds__(32 * RPB) void siddon_accum_kernel(
        float* __restrict__ out) {
    __shared__ int4 s_t4[RPB][NSTEPS / 2 + 1];

    int yy  = threadIdx.y;       // ray within block (== warp id)
    int x   = threadIdx.x;       // lane: covers v = 2x, 2x+1
    int ray = blockIdx.x * RPB + yy;

    int cnt  = g_cnt[ray];       // uniform per warp -> broadcast load
    int base = ray * NSTEPS;

    int2* s_t = (int2*)&s_t4[yy][0];
    for (int n = x; n < cnt; n += 32)
        s_t[n] = g_trace[base + n];
    __syncwarp();

    float a0x = 0.0f, a0y = 0.0f, a1x = 0.0f, a1y = 0.0f;

    int n = 0;
    for (; n + 1 < cnt; n += 2) {
        int4 e = s_t4[yy][n >> 1];      // two entries: (e.x,e.y), (e.z,e.w)
        float2 v0 = __half22float2(g_volh[(e.x >> 1) + x]);
        float2 v1 = __half22float2(g_volh[(e.z >> 1) + x]);
        float  w0 = __int_as_float(e.y);
        float  w1 = __int_as_float(e.w);
        a0x += v0.x * w0;  a0y += v0.y * w0;
        a1x += v1.x * w1;  a1y += v1.y * w1;
    }
    if (n < cnt) {
        int2 e = s_t[n];
        float2 v = __half22float2(g_volh[(e.x >> 1) + x]);
        float  w = __int_as_float(e.y);
        a0x += v.x * w;  a0y += v.y * w;
    }

    int a  = ray / Ud;
    int ui = ray % Ud;
    float2 res;
    res.x = a0x + a1x;
    res.y = a0y + a1y;
    // output layout (B,C,U,A,V): float2 index = (u*A + a)*32 + lane
    ((float2*)out)[(ui * Ad + a) * 32 + x] = res;
}

extern "C" void kernel_launch(void* const* d_in, const int* in_sizes, int n_in,
                              void* d_out, int out_size) {
    const float* vol = (const float*)d_in[0];
    float* out = (float*)d_out;

    siddon_trace_conv_kernel<<<TRACE_BLOCKS + CONV_BLOCKS, 64>>>(vol);

    dim3 blk(32, RPB);                 // 128 threads
    dim3 grd(NRAYS / RPB);             // 2160 blocks
    siddon_accum_kernel<<<grd, blk>>>(out);
}